// round 1
// baseline (speedup 1.0000x reference)
#include <cuda_runtime.h>
#include <cstdint>

#define S_LEN 2048
#define DMODEL 1024
#define NHEADS 16
#define DK 64

// -------- scratch (static device globals; no allocation allowed) ----------
__device__ float g_Q[S_LEN * DMODEL];
__device__ float g_K[S_LEN * DMODEL];
__device__ float g_V[S_LEN * DMODEL];
__device__ float g_ctx[S_LEN * DMODEL];
__device__ float g_rowsum[NHEADS * S_LEN];

// ---------------------------------------------------------------------------
// GEMM: C[M,N] = A[M,K] @ B[N,K]^T (+ optional bias). M=2048 or via grid.
// BM=BN=128, BK=16, 256 threads, 8x8 per-thread strided register tile.
// ---------------------------------------------------------------------------
__global__ __launch_bounds__(256) void gemm_abT(
    const float* __restrict__ A, const float* __restrict__ B,
    float* __restrict__ C, const float* __restrict__ bias, int Kdim, int Ndim)
{
    const int m0 = blockIdx.x * 128;
    const int n0 = blockIdx.y * 128;

    __shared__ float As[16][129];
    __shared__ float Bs[16][129];

    const int tid = threadIdx.x;
    const int tx = tid & 15;
    const int ty = tid >> 4;
    const int lk = tid & 15;   // k index for loads
    const int lm = tid >> 4;   // row base for loads

    float acc[8][8];
#pragma unroll
    for (int i = 0; i < 8; ++i)
#pragma unroll
        for (int j = 0; j < 8; ++j) acc[i][j] = 0.f;

    for (int kt = 0; kt < Kdim; kt += 16) {
        __syncthreads();
#pragma unroll
        for (int i = 0; i < 8; ++i) {
            As[lk][lm + 16 * i] = A[(size_t)(m0 + lm + 16 * i) * Kdim + kt + lk];
            Bs[lk][lm + 16 * i] = B[(size_t)(n0 + lm + 16 * i) * Kdim + kt + lk];
        }
        __syncthreads();
#pragma unroll
        for (int kk = 0; kk < 16; ++kk) {
            float a[8], b[8];
#pragma unroll
            for (int i = 0; i < 8; ++i) a[i] = As[kk][ty + 16 * i];
#pragma unroll
            for (int j = 0; j < 8; ++j) b[j] = Bs[kk][tx + 16 * j];
#pragma unroll
            for (int i = 0; i < 8; ++i)
#pragma unroll
                for (int j = 0; j < 8; ++j) acc[i][j] += a[i] * b[j];
        }
    }

#pragma unroll
    for (int j = 0; j < 8; ++j) {
        const int n = n0 + tx + 16 * j;
        const float bv = bias ? bias[n] : 0.f;
#pragma unroll
        for (int i = 0; i < 8; ++i) {
            C[(size_t)(m0 + ty + 16 * i) * Ndim + n] = acc[i][j] + bv;
        }
    }
}

// ---------------------------------------------------------------------------
// RoPE applied in-place to Q and K. One thread per (s, head, pair d<32).
// ---------------------------------------------------------------------------
__global__ __launch_bounds__(256) void rope_kernel(float* __restrict__ Q,
                                                   float* __restrict__ Km)
{
    const int idx = blockIdx.x * blockDim.x + threadIdx.x;   // < 2048*512
    const int s = idx >> 9;
    const int r = idx & 511;
    const int h = r >> 5;
    const int d = r & 31;

    // inv_freq = 10000^{-d/32} = exp(-d * ln(10000)/32)
    const float inv_freq = expf(-(float)d * 0.28782313662425572f);
    const float ang = (float)s * inv_freq;
    float c, si;
    sincosf(ang, &si, &c);

    const int base = s * DMODEL + h * DK + d;

    float x1 = Q[base], x2 = Q[base + 32];
    Q[base]      = x1 * c - x2 * si;
    Q[base + 32] = x2 * c + x1 * si;

    x1 = Km[base]; x2 = Km[base + 32];
    Km[base]      = x1 * c - x2 * si;
    Km[base + 32] = x2 * c + x1 * si;
}

// ---------------------------------------------------------------------------
// Attention: per block = (64 q rows, one head). Single pass, max-free softmax:
//   e = exp(score/8) written unnormalized to attn, summed per row,
//   ctx accumulated with unnormalized e and scaled by 1/rowsum at the end.
// smem: Qs[d][q], Bs (K as [d][k], then V as [k][dd]), Ps[q][k]. 48KB total.
// ---------------------------------------------------------------------------
__global__ __launch_bounds__(256) void attn_kernel(
    const float* __restrict__ Q, const float* __restrict__ Km,
    const float* __restrict__ V, float* __restrict__ attn,
    float* __restrict__ ctx, float* __restrict__ rowsum)
{
    const int h = blockIdx.y;
    const int q0 = blockIdx.x * 64;
    const int tid = threadIdx.x;
    const int tx = tid & 15;
    const int ty = tid >> 4;

    __shared__ float Qs[64][64];  // [d][q]
    __shared__ float Bs[64][64];  // K phase: [d][k];  V phase: [k][dd]
    __shared__ float Ps[64][64];  // [q][k]

    // load Q tile (float4 per thread, 4 iters)
#pragma unroll
    for (int it = 0; it < 4; ++it) {
        const int q = ty + 16 * it;
        const float4 v4 = *(const float4*)&Q[(size_t)(q0 + q) * DMODEL + h * DK + 4 * tx];
        Qs[4 * tx + 0][q] = v4.x;
        Qs[4 * tx + 1][q] = v4.y;
        Qs[4 * tx + 2][q] = v4.z;
        Qs[4 * tx + 3][q] = v4.w;
    }

    float Ssum[4] = {0.f, 0.f, 0.f, 0.f};
    float acc[4][4];
#pragma unroll
    for (int i = 0; i < 4; ++i)
#pragma unroll
        for (int j = 0; j < 4; ++j) acc[i][j] = 0.f;

    const float scale = 0.125f;   // 1/sqrt(64)

    for (int kt = 0; kt < 32; ++kt) {
        __syncthreads();  // Bs (V of prev iter) fully consumed; Qs ready on iter 0
        // load K tile: Bs[d][k]
#pragma unroll
        for (int it = 0; it < 4; ++it) {
            const int k = ty + 16 * it;
            const float4 v4 = *(const float4*)&Km[(size_t)(kt * 64 + k) * DMODEL + h * DK + 4 * tx];
            Bs[4 * tx + 0][k] = v4.x;
            Bs[4 * tx + 1][k] = v4.y;
            Bs[4 * tx + 2][k] = v4.z;
            Bs[4 * tx + 3][k] = v4.w;
        }
        __syncthreads();

        // scores: sc[i][j] = sum_d Qs[d][ty+16i] * Bs[d][tx+16j]
        float sc[4][4];
#pragma unroll
        for (int i = 0; i < 4; ++i)
#pragma unroll
            for (int j = 0; j < 4; ++j) sc[i][j] = 0.f;

#pragma unroll 8
        for (int d = 0; d < 64; ++d) {
            float a[4], b[4];
#pragma unroll
            for (int i = 0; i < 4; ++i) a[i] = Qs[d][ty + 16 * i];
#pragma unroll
            for (int j = 0; j < 4; ++j) b[j] = Bs[d][tx + 16 * j];
#pragma unroll
            for (int i = 0; i < 4; ++i)
#pragma unroll
                for (int j = 0; j < 4; ++j) sc[i][j] += a[i] * b[j];
        }

        // exp, write unnormalized attn, stash in Ps, accumulate row sums
#pragma unroll
        for (int i = 0; i < 4; ++i) {
            const int qr = q0 + ty + 16 * i;
#pragma unroll
            for (int j = 0; j < 4; ++j) {
                const float e = __expf(sc[i][j] * scale);
                Ps[ty + 16 * i][tx + 16 * j] = e;
                if (attn)
                    attn[((size_t)h * S_LEN + qr) * S_LEN + kt * 64 + tx + 16 * j] = e;
                Ssum[i] += e;
            }
        }
        __syncthreads();  // scores done reading Bs(K); Ps written

        // load V tile: Bs[k][dd]
#pragma unroll
        for (int it = 0; it < 4; ++it) {
            const int k = ty + 16 * it;
            const float4 v4 = *(const float4*)&V[(size_t)(kt * 64 + k) * DMODEL + h * DK + 4 * tx];
            *(float4*)&Bs[k][4 * tx] = v4;
        }
        __syncthreads();

        // ctx += Ps @ V
#pragma unroll 8
        for (int kk = 0; kk < 64; ++kk) {
            float a[4], b[4];
#pragma unroll
            for (int i = 0; i < 4; ++i) a[i] = Ps[ty + 16 * i][kk];
#pragma unroll
            for (int j = 0; j < 4; ++j) b[j] = Bs[kk][tx + 16 * j];
#pragma unroll
            for (int i = 0; i < 4; ++i)
#pragma unroll
                for (int j = 0; j < 4; ++j) acc[i][j] += a[i] * b[j];
        }
    }

    // reduce row sums across the 16 lanes that share a row, write ctx & rowsum
#pragma unroll
    for (int i = 0; i < 4; ++i) {
        float s = Ssum[i];
        s += __shfl_xor_sync(0xffffffffu, s, 8);
        s += __shfl_xor_sync(0xffffffffu, s, 4);
        s += __shfl_xor_sync(0xffffffffu, s, 2);
        s += __shfl_xor_sync(0xffffffffu, s, 1);
        const float inv = 1.f / s;
        const int qr = q0 + ty + 16 * i;
        if (tx == 0) rowsum[h * S_LEN + qr] = s;
#pragma unroll
        for (int j = 0; j < 4; ++j)
            ctx[(size_t)qr * DMODEL + h * DK + tx + 16 * j] = acc[i][j] * inv;
    }
}

// ---------------------------------------------------------------------------
// Normalize attn in a streaming pass: attn[h,q,:] *= 1/rowsum[h,q]
// ---------------------------------------------------------------------------
__global__ __launch_bounds__(256) void normalize_attn(float* __restrict__ attn,
                                                      const float* __restrict__ rowsum)
{
    const size_t idx4 = (size_t)blockIdx.x * blockDim.x + threadIdx.x;  // float4 idx
    const size_t base = idx4 * 4;
    const int row = (int)(base >> 11);         // h*2048 + q  (0..32767)
    const float inv = 1.f / rowsum[row];
    float4 v = *(float4*)&attn[base];
    v.x *= inv; v.y *= inv; v.z *= inv; v.w *= inv;
    *(float4*)&attn[base] = v;
}

// ---------------------------------------------------------------------------

extern "C" void kernel_launch(void* const* d_in, const int* in_sizes, int n_in,
                              void* d_out, int out_size)
{
    const float* q_in = (const float*)d_in[0];
    const float* k_in = (const float*)d_in[1];
    const float* v_in = (const float*)d_in[2];
    const float* w_q  = (const float*)d_in[3];
    const float* w_k  = (const float*)d_in[4];
    const float* w_v  = (const float*)d_in[5];
    const float* w_o  = (const float*)d_in[6];
    const float* b_o  = (const float*)d_in[7];
    float* out = (float*)d_out;

    const long long OUT_E  = (long long)S_LEN * DMODEL;              // 2,097,152
    const long long ATTN_E = (long long)NHEADS * S_LEN * S_LEN;      // 67,108,864
    float* attn = nullptr;
    if ((long long)out_size >= OUT_E + ATTN_E) attn = out + OUT_E;

    float *pQ, *pK, *pV, *pCtx, *pRS;
    cudaGetSymbolAddress((void**)&pQ,   g_Q);
    cudaGetSymbolAddress((void**)&pK,   g_K);
    cudaGetSymbolAddress((void**)&pV,   g_V);
    cudaGetSymbolAddress((void**)&pCtx, g_ctx);
    cudaGetSymbolAddress((void**)&pRS,  g_rowsum);

    const dim3 gemm_grid(S_LEN / 128, DMODEL / 128);

    // QKV projections: X @ W^T
    gemm_abT<<<gemm_grid, 256>>>(q_in, w_q, pQ, nullptr, DMODEL, DMODEL);
    gemm_abT<<<gemm_grid, 256>>>(k_in, w_k, pK, nullptr, DMODEL, DMODEL);
    gemm_abT<<<gemm_grid, 256>>>(v_in, w_v, pV, nullptr, DMODEL, DMODEL);

    // RoPE on Q, K
    rope_kernel<<<(S_LEN * 512) / 256, 256>>>(pQ, pK);

    // attention (writes unnormalized attn, normalized ctx, rowsums)
    attn_kernel<<<dim3(S_LEN / 64, NHEADS), 256>>>(pQ, pK, pV, attn, pCtx, pRS);

    // normalize attn output
    if (attn)
        normalize_attn<<<(int)(ATTN_E / 4 / 256), 256>>>(attn, pRS);

    // output projection with bias
    gemm_abT<<<gemm_grid, 256>>>(pCtx, w_o, out, b_o, DMODEL, DMODEL);
}

// round 2
// speedup vs baseline: 1.8126x; 1.8126x over previous
#include <cuda_runtime.h>
#include <cstdint>

#define S_LEN 2048
#define DMODEL 1024
#define NHEADS 16
#define DK 64

// -------- scratch (static device globals; no allocation allowed) ----------
__device__ float g_Qt[DMODEL * S_LEN];   // [h*64+d][s]  (per-head transposed)
__device__ float g_Kt[DMODEL * S_LEN];   // [h*64+d][s]
__device__ float g_V [S_LEN * DMODEL];   // [s][e] normal
__device__ float g_ctx[S_LEN * DMODEL];  // [s][e] normal

#define ATTN_SMEM ((64 * 132 + 64 * 68 + 128 * 68) * 4)   // 86016 B

// ---------------------------------------------------------------------------
// GEMM body: C = A[2048,1024] @ B[1024,1024]^T (+bias).
// 128x128 tile, BK=16, 256 threads, 8x8 per-thread (two 4-wide float4 spans).
// transOut=1 writes C transposed: Ct[n][m] (row stride 2048).
// ---------------------------------------------------------------------------
__device__ __forceinline__ void gemm_body(
    const float* __restrict__ A, const float* __restrict__ B,
    float* __restrict__ C, const float* __restrict__ bias, int transOut)
{
    const int m0 = blockIdx.x * 128;
    const int n0 = blockIdx.y * 128;

    __shared__ float As[16][132];
    __shared__ float Bs[16][132];

    const int tid = threadIdx.x;
    const int tx  = tid & 15;
    const int ty  = tid >> 4;
    const int lk4 = tid & 3;     // k-quad: k = 4*lk4 .. +3
    const int lm  = tid >> 2;    // row 0..63 (also +64)

    const float* Ar0 = A + (size_t)(m0 + lm) * 1024 + 4 * lk4;
    const float* Ar1 = Ar0 + (size_t)64 * 1024;
    const float* Br0 = B + (size_t)(n0 + lm) * 1024 + 4 * lk4;
    const float* Br1 = Br0 + (size_t)64 * 1024;

    float4 pa0 = *(const float4*)Ar0;
    float4 pa1 = *(const float4*)Ar1;
    float4 pb0 = *(const float4*)Br0;
    float4 pb1 = *(const float4*)Br1;

    float acc[8][8];
#pragma unroll
    for (int i = 0; i < 8; ++i)
#pragma unroll
        for (int j = 0; j < 8; ++j) acc[i][j] = 0.f;

    for (int kt = 0; kt < 64; ++kt) {
        __syncthreads();
        As[4 * lk4 + 0][lm]      = pa0.x;
        As[4 * lk4 + 1][lm]      = pa0.y;
        As[4 * lk4 + 2][lm]      = pa0.z;
        As[4 * lk4 + 3][lm]      = pa0.w;
        As[4 * lk4 + 0][lm + 64] = pa1.x;
        As[4 * lk4 + 1][lm + 64] = pa1.y;
        As[4 * lk4 + 2][lm + 64] = pa1.z;
        As[4 * lk4 + 3][lm + 64] = pa1.w;
        Bs[4 * lk4 + 0][lm]      = pb0.x;
        Bs[4 * lk4 + 1][lm]      = pb0.y;
        Bs[4 * lk4 + 2][lm]      = pb0.z;
        Bs[4 * lk4 + 3][lm]      = pb0.w;
        Bs[4 * lk4 + 0][lm + 64] = pb1.x;
        Bs[4 * lk4 + 1][lm + 64] = pb1.y;
        Bs[4 * lk4 + 2][lm + 64] = pb1.z;
        Bs[4 * lk4 + 3][lm + 64] = pb1.w;
        __syncthreads();

        if (kt < 63) {
            pa0 = *(const float4*)(Ar0 + (kt + 1) * 16);
            pa1 = *(const float4*)(Ar1 + (kt + 1) * 16);
            pb0 = *(const float4*)(Br0 + (kt + 1) * 16);
            pb1 = *(const float4*)(Br1 + (kt + 1) * 16);
        }

#pragma unroll
        for (int kk = 0; kk < 16; ++kk) {
            float4 a0 = *(const float4*)&As[kk][4 * ty];
            float4 a1 = *(const float4*)&As[kk][64 + 4 * ty];
            float4 b0 = *(const float4*)&Bs[kk][4 * tx];
            float4 b1 = *(const float4*)&Bs[kk][64 + 4 * tx];
            float a[8] = {a0.x, a0.y, a0.z, a0.w, a1.x, a1.y, a1.z, a1.w};
            float b[8] = {b0.x, b0.y, b0.z, b0.w, b1.x, b1.y, b1.z, b1.w};
#pragma unroll
            for (int i = 0; i < 8; ++i)
#pragma unroll
                for (int j = 0; j < 8; ++j) acc[i][j] += a[i] * b[j];
        }
    }

    if (!transOut) {
#pragma unroll
        for (int iq = 0; iq < 2; ++iq)
#pragma unroll
            for (int ii = 0; ii < 4; ++ii) {
                const int m = m0 + iq * 64 + 4 * ty + ii;
#pragma unroll
                for (int jq = 0; jq < 2; ++jq) {
                    const int n = n0 + jq * 64 + 4 * tx;
                    float4 v;
                    v.x = acc[iq * 4 + ii][jq * 4 + 0];
                    v.y = acc[iq * 4 + ii][jq * 4 + 1];
                    v.z = acc[iq * 4 + ii][jq * 4 + 2];
                    v.w = acc[iq * 4 + ii][jq * 4 + 3];
                    if (bias) {
                        v.x += bias[n + 0]; v.y += bias[n + 1];
                        v.z += bias[n + 2]; v.w += bias[n + 3];
                    }
                    *(float4*)&C[(size_t)m * 1024 + n] = v;
                }
            }
    } else {
#pragma unroll
        for (int jq = 0; jq < 2; ++jq)
#pragma unroll
            for (int jj = 0; jj < 4; ++jj) {
                const int n = n0 + jq * 64 + 4 * tx + jj;
#pragma unroll
                for (int iq = 0; iq < 2; ++iq) {
                    float4 v;
                    v.x = acc[iq * 4 + 0][jq * 4 + jj];
                    v.y = acc[iq * 4 + 1][jq * 4 + jj];
                    v.z = acc[iq * 4 + 2][jq * 4 + jj];
                    v.w = acc[iq * 4 + 3][jq * 4 + jj];
                    *(float4*)&C[(size_t)n * 2048 + m0 + iq * 64 + 4 * ty] = v;
                }
            }
    }
}

__global__ __launch_bounds__(256) void gemm_qkv(
    const float* __restrict__ q, const float* __restrict__ k,
    const float* __restrict__ v,
    const float* __restrict__ wq, const float* __restrict__ wk,
    const float* __restrict__ wv,
    float* __restrict__ Qt, float* __restrict__ Kt, float* __restrict__ Vn)
{
    if (blockIdx.z == 0)      gemm_body(q, wq, Qt, nullptr, 1);
    else if (blockIdx.z == 1) gemm_body(k, wk, Kt, nullptr, 1);
    else                      gemm_body(v, wv, Vn, nullptr, 0);
}

__global__ __launch_bounds__(256) void gemm_out(
    const float* __restrict__ A, const float* __restrict__ B,
    float* __restrict__ C, const float* __restrict__ bias)
{
    gemm_body(A, B, C, bias, 0);
}

// ---------------------------------------------------------------------------
// RoPE in-place on transposed Q/K: rows (h*64+d) and (h*64+d+32), d<32.
// One thread per float4 along s. 262144 threads.
// ---------------------------------------------------------------------------
__global__ __launch_bounds__(256) void rope_t(float* __restrict__ Qt,
                                              float* __restrict__ Kt)
{
    const int idx  = blockIdx.x * 256 + threadIdx.x;   // < 262144
    const int s4   = idx & 511;
    const int rest = idx >> 9;
    const int d    = rest & 31;
    const int h    = rest >> 5;

    const size_t r1 = (size_t)(h * 64 + d) * 2048 + 4 * s4;
    const size_t r2 = r1 + (size_t)32 * 2048;

    const float inv_freq = expf(-(float)d * 0.28782313662425572f);

    float4 q1 = *(float4*)&Qt[r1];
    float4 q2 = *(float4*)&Qt[r2];
    float4 k1 = *(float4*)&Kt[r1];
    float4 k2 = *(float4*)&Kt[r2];

    float co[4], si[4];
#pragma unroll
    for (int c = 0; c < 4; ++c)
        sincosf((float)(4 * s4 + c) * inv_freq, &si[c], &co[c]);

    float4 o1, o2;
    o1.x = q1.x * co[0] - q2.x * si[0];  o2.x = q2.x * co[0] + q1.x * si[0];
    o1.y = q1.y * co[1] - q2.y * si[1];  o2.y = q2.y * co[1] + q1.y * si[1];
    o1.z = q1.z * co[2] - q2.z * si[2];  o2.z = q2.z * co[2] + q1.z * si[2];
    o1.w = q1.w * co[3] - q2.w * si[3];  o2.w = q2.w * co[3] + q1.w * si[3];
    *(float4*)&Qt[r1] = o1;
    *(float4*)&Qt[r2] = o2;

    o1.x = k1.x * co[0] - k2.x * si[0];  o2.x = k2.x * co[0] + k1.x * si[0];
    o1.y = k1.y * co[1] - k2.y * si[1];  o2.y = k2.y * co[1] + k1.y * si[1];
    o1.z = k1.z * co[2] - k2.z * si[2];  o2.z = k2.z * co[2] + k1.z * si[2];
    o1.w = k1.w * co[3] - k2.w * si[3];  o2.w = k2.w * co[3] + k1.w * si[3];
    *(float4*)&Kt[r1] = o1;
    *(float4*)&Kt[r2] = o2;
}

// ---------------------------------------------------------------------------
// Attention: block = (128 q rows, one head), 32 k-tiles of 64. Max-free
// single-pass softmax; attn written unnormalized then rescaled in-kernel
// (each thread rescales only values it wrote itself -> no sync needed).
// Thread tile: 8 q (4*ty+i and 64+4*ty+i) x 4 k/dd (4*tx+j).
// ---------------------------------------------------------------------------
__global__ __launch_bounds__(256, 2) void attn_kernel(
    const float* __restrict__ Qt, const float* __restrict__ Kt,
    const float* __restrict__ V, float* __restrict__ attn,
    float* __restrict__ ctx)
{
    extern __shared__ float sm[];
    float* Qs = sm;                    // [64][132]  d-major, 128 q cols
    float* Bs = sm + 64 * 132;         // [64][68]   K: [d][k] / V: [k][dd]
    float* Ps = Bs + 64 * 68;          // [128][68]  [q][k]

    const int h  = blockIdx.y;
    const int q0 = blockIdx.x * 128;
    const int tid = threadIdx.x;
    const int tx = tid & 15;
    const int ty = tid >> 4;

    // load Q tile: Qs[d][q], float4 over q
#pragma unroll
    for (int it = 0; it < 8; ++it) {
        const int idx = it * 256 + tid;
        const int d = idx >> 5, c = idx & 31;
        *(float4*)&Qs[d * 132 + 4 * c] =
            *(const float4*)&Qt[(size_t)(h * 64 + d) * 2048 + q0 + 4 * c];
    }

    float acc[8][4];
    float Ssum[8];
#pragma unroll
    for (int i = 0; i < 8; ++i) {
        Ssum[i] = 0.f;
#pragma unroll
        for (int j = 0; j < 4; ++j) acc[i][j] = 0.f;
    }

    for (int kt = 0; kt < 32; ++kt) {
        const int k0 = kt * 64;
        __syncthreads();
        // K tile -> Bs[d][k], float4 over k
#pragma unroll
        for (int it = 0; it < 4; ++it) {
            const int idx = it * 256 + tid;
            const int d = idx >> 4, c = idx & 15;
            *(float4*)&Bs[d * 68 + 4 * c] =
                *(const float4*)&Kt[(size_t)(h * 64 + d) * 2048 + k0 + 4 * c];
        }
        __syncthreads();

        float sc[8][4];
#pragma unroll
        for (int i = 0; i < 8; ++i)
#pragma unroll
            for (int j = 0; j < 4; ++j) sc[i][j] = 0.f;

#pragma unroll 8
        for (int d = 0; d < 64; ++d) {
            float4 a0 = *(const float4*)&Qs[d * 132 + 4 * ty];
            float4 a1 = *(const float4*)&Qs[d * 132 + 64 + 4 * ty];
            float4 b  = *(const float4*)&Bs[d * 68 + 4 * tx];
            float a[8] = {a0.x, a0.y, a0.z, a0.w, a1.x, a1.y, a1.z, a1.w};
#pragma unroll
            for (int i = 0; i < 8; ++i) {
                sc[i][0] += a[i] * b.x;
                sc[i][1] += a[i] * b.y;
                sc[i][2] += a[i] * b.z;
                sc[i][3] += a[i] * b.w;
            }
        }

        // exp -> Ps + unnormalized attn + row sums
#pragma unroll
        for (int i = 0; i < 8; ++i) {
            const int row = ((i & 4) << 4) + 4 * ty + (i & 3);
            float4 e;
            e.x = __expf(sc[i][0] * 0.125f);
            e.y = __expf(sc[i][1] * 0.125f);
            e.z = __expf(sc[i][2] * 0.125f);
            e.w = __expf(sc[i][3] * 0.125f);
            Ssum[i] += (e.x + e.y) + (e.z + e.w);
            *(float4*)&Ps[row * 68 + 4 * tx] = e;
            if (attn)
                *(float4*)&attn[(size_t)(h * 2048 + q0 + row) * 2048 + k0 + 4 * tx] = e;
        }
        __syncthreads();
        // V tile -> Bs[k][dd], float4 over dd
#pragma unroll
        for (int it = 0; it < 4; ++it) {
            const int idx = it * 256 + tid;
            const int k = idx >> 4, c = idx & 15;
            *(float4*)&Bs[k * 68 + 4 * c] =
                *(const float4*)&V[(size_t)(k0 + k) * 1024 + h * 64 + 4 * c];
        }
        __syncthreads();

#pragma unroll 8
        for (int kk = 0; kk < 64; ++kk) {
            float4 b = *(const float4*)&Bs[kk * 68 + 4 * tx];
#pragma unroll
            for (int i = 0; i < 8; ++i) {
                const int row = ((i & 4) << 4) + 4 * ty + (i & 3);
                const float a = Ps[row * 68 + kk];
                acc[i][0] += a * b.x;
                acc[i][1] += a * b.y;
                acc[i][2] += a * b.z;
                acc[i][3] += a * b.w;
            }
        }
    }

    // reduce row sums over 16 lanes sharing ty, write ctx, normalize attn
    float inv[8];
#pragma unroll
    for (int i = 0; i < 8; ++i) {
        float s = Ssum[i];
        s += __shfl_xor_sync(0xffffffffu, s, 8);
        s += __shfl_xor_sync(0xffffffffu, s, 4);
        s += __shfl_xor_sync(0xffffffffu, s, 2);
        s += __shfl_xor_sync(0xffffffffu, s, 1);
        inv[i] = 1.f / s;
        const int row = ((i & 4) << 4) + 4 * ty + (i & 3);
        float4 c4;
        c4.x = acc[i][0] * inv[i];
        c4.y = acc[i][1] * inv[i];
        c4.z = acc[i][2] * inv[i];
        c4.w = acc[i][3] * inv[i];
        *(float4*)&ctx[(size_t)(q0 + row) * 1024 + h * 64 + 4 * tx] = c4;
    }

    if (attn) {
#pragma unroll
        for (int i = 0; i < 8; ++i) {
            const int row = ((i & 4) << 4) + 4 * ty + (i & 3);
            float* p = &attn[(size_t)(h * 2048 + q0 + row) * 2048 + 4 * tx];
            const float s = inv[i];
#pragma unroll 8
            for (int kt = 0; kt < 32; ++kt) {
                float4 v = *(float4*)&p[kt * 64];
                v.x *= s; v.y *= s; v.z *= s; v.w *= s;
                *(float4*)&p[kt * 64] = v;
            }
        }
    }
}

// ---------------------------------------------------------------------------

extern "C" void kernel_launch(void* const* d_in, const int* in_sizes, int n_in,
                              void* d_out, int out_size)
{
    const float* q_in = (const float*)d_in[0];
    const float* k_in = (const float*)d_in[1];
    const float* v_in = (const float*)d_in[2];
    const float* w_q  = (const float*)d_in[3];
    const float* w_k  = (const float*)d_in[4];
    const float* w_v  = (const float*)d_in[5];
    const float* w_o  = (const float*)d_in[6];
    const float* b_o  = (const float*)d_in[7];
    float* out = (float*)d_out;

    const long long OUT_E  = (long long)S_LEN * DMODEL;
    const long long ATTN_E = (long long)NHEADS * S_LEN * S_LEN;
    float* attn = nullptr;
    if ((long long)out_size >= OUT_E + ATTN_E) attn = out + OUT_E;

    float *pQt, *pKt, *pV, *pCtx;
    cudaGetSymbolAddress((void**)&pQt,  g_Qt);
    cudaGetSymbolAddress((void**)&pKt,  g_Kt);
    cudaGetSymbolAddress((void**)&pV,   g_V);
    cudaGetSymbolAddress((void**)&pCtx, g_ctx);

    cudaFuncSetAttribute(attn_kernel,
                         cudaFuncAttributeMaxDynamicSharedMemorySize, ATTN_SMEM);

    // fused QKV projections (z: 0=Q->Qt(T), 1=K->Kt(T), 2=V normal)
    gemm_qkv<<<dim3(16, 8, 3), 256>>>(q_in, k_in, v_in, w_q, w_k, w_v,
                                      pQt, pKt, pV);
    // RoPE on transposed Q/K
    rope_t<<<1024, 256>>>(pQt, pKt);
    // attention (fused unnormalized-write + in-kernel normalization)
    attn_kernel<<<dim3(16, 16), 256, ATTN_SMEM>>>(pQt, pKt, pV, attn, pCtx);
    // output projection with bias
    gemm_out<<<dim3(16, 8), 256>>>(pCtx, w_o, out, b_o);
}

// round 3
// speedup vs baseline: 2.5712x; 1.4185x over previous
#include <cuda_runtime.h>
#include <cuda_bf16.h>
#include <cstdint>

#define S_LEN 2048
#define DMODEL 1024
#define NHEADS 16
#define DK 64

typedef __nv_bfloat16 bf16;

// ------------------------- scratch (device globals) ------------------------
__device__ float g_Qf[S_LEN * DMODEL];
__device__ float g_Kf[S_LEN * DMODEL];
__device__ float g_Vf[S_LEN * DMODEL];

__device__ bf16 g_qh[S_LEN * DMODEL], g_ql[S_LEN * DMODEL];
__device__ bf16 g_kh[S_LEN * DMODEL], g_kl[S_LEN * DMODEL];
__device__ bf16 g_vh[S_LEN * DMODEL], g_vl[S_LEN * DMODEL];
__device__ bf16 g_wqh[DMODEL * DMODEL], g_wql[DMODEL * DMODEL];
__device__ bf16 g_wkh[DMODEL * DMODEL], g_wkl[DMODEL * DMODEL];
__device__ bf16 g_wvh[DMODEL * DMODEL], g_wvl[DMODEL * DMODEL];
__device__ bf16 g_woh[DMODEL * DMODEL], g_wol[DMODEL * DMODEL];

__device__ bf16 g_Qh[S_LEN * DMODEL], g_Ql[S_LEN * DMODEL];   // rope'd Q
__device__ bf16 g_Kh[S_LEN * DMODEL], g_Kl[S_LEN * DMODEL];   // rope'd K
__device__ bf16 g_Vth[DMODEL * S_LEN], g_Vtl[DMODEL * S_LEN]; // V transposed
__device__ bf16 g_ctxh[S_LEN * DMODEL], g_ctxl[S_LEN * DMODEL];

// ------------------------------- helpers -----------------------------------
__device__ __forceinline__ void mma_bf16(float d[4], const uint32_t a[4],
                                         const uint32_t b[2]) {
    asm volatile(
        "mma.sync.aligned.m16n8k16.row.col.f32.bf16.bf16.f32 "
        "{%0,%1,%2,%3}, {%4,%5,%6,%7}, {%8,%9}, {%0,%1,%2,%3};"
        : "+f"(d[0]), "+f"(d[1]), "+f"(d[2]), "+f"(d[3])
        : "r"(a[0]), "r"(a[1]), "r"(a[2]), "r"(a[3]), "r"(b[0]), "r"(b[1]));
}

// pack (elem0=lo_addr, elem1) into bf16x2 register
__device__ __forceinline__ uint32_t pack_bf16(float e0, float e1) {
    uint32_t r;
    asm("cvt.rn.bf16x2.f32 %0, %1, %2;" : "=r"(r) : "f"(e1), "f"(e0));
    return r;
}

__device__ __forceinline__ void split2(float x, bf16& h, bf16& l) {
    h = __float2bfloat16_rn(x);
    l = __float2bfloat16_rn(x - __bfloat162float(h));
}

// ------------------------- convert inputs to bf16 hi/lo --------------------
__global__ __launch_bounds__(256) void conv_kernel(
    const float* __restrict__ q, const float* __restrict__ k,
    const float* __restrict__ v, const float* __restrict__ wq,
    const float* __restrict__ wk, const float* __restrict__ wv,
    const float* __restrict__ wo)
{
    const int z = blockIdx.z;
    const float* src;
    bf16 *dh, *dl;
    int n;
    switch (z) {
    case 0: src = q;  dh = g_qh;  dl = g_ql;  n = S_LEN * DMODEL; break;
    case 1: src = k;  dh = g_kh;  dl = g_kl;  n = S_LEN * DMODEL; break;
    case 2: src = v;  dh = g_vh;  dl = g_vl;  n = S_LEN * DMODEL; break;
    case 3: src = wq; dh = g_wqh; dl = g_wql; n = DMODEL * DMODEL; break;
    case 4: src = wk; dh = g_wkh; dl = g_wkl; n = DMODEL * DMODEL; break;
    case 5: src = wv; dh = g_wvh; dl = g_wvl; n = DMODEL * DMODEL; break;
    default: src = wo; dh = g_woh; dl = g_wol; n = DMODEL * DMODEL; break;
    }
    const int i = (blockIdx.x * 256 + threadIdx.x) * 4;
    if (i >= n) return;
    float4 x = *(const float4*)&src[i];
    bf16 h0, h1, h2, h3, l0, l1, l2, l3;
    split2(x.x, h0, l0); split2(x.y, h1, l1);
    split2(x.z, h2, l2); split2(x.w, h3, l3);
    uint32_t* ph = (uint32_t*)&dh[i];
    uint32_t* pl = (uint32_t*)&dl[i];
    ph[0] = pack_bf16(__bfloat162float(h0), __bfloat162float(h1));
    ph[1] = pack_bf16(__bfloat162float(h2), __bfloat162float(h3));
    pl[0] = pack_bf16(__bfloat162float(l0), __bfloat162float(l1));
    pl[1] = pack_bf16(__bfloat162float(l2), __bfloat162float(l3));
}

// ------------------- bf16x3 GEMM: C = A @ B^T (+bias) ----------------------
// A: [2048][1024] bf16 hi/lo, B: [1024][1024] bf16 hi/lo, C fp32 [2048][1024]
// block tile 128x128, 8 warps, warp tile 32x64, k-chunk 32.
__device__ __forceinline__ void gemm_mma_body(
    const bf16* __restrict__ Ah, const bf16* __restrict__ Al,
    const bf16* __restrict__ Bh, const bf16* __restrict__ Bl,
    float* __restrict__ C, const float* __restrict__ bias)
{
    const int m0 = blockIdx.x * 128;
    const int n0 = blockIdx.y * 128;

    __shared__ bf16 sAh[128][40], sAl[128][40], sBh[128][40], sBl[128][40];

    const int tid = threadIdx.x;
    const int w = tid >> 5, lane = tid & 31;
    const int g = lane >> 2, qq = lane & 3;
    const int wm = (w >> 1) * 32, wn = (w & 1) * 64;

    float acc[2][8][4];
#pragma unroll
    for (int mt = 0; mt < 2; ++mt)
#pragma unroll
        for (int nt = 0; nt < 8; ++nt)
#pragma unroll
            for (int e = 0; e < 4; ++e) acc[mt][nt][e] = 0.f;

    const int lr = tid >> 1;
    const int lc = (tid & 1) * 16;
    const bf16* pAh = Ah + (size_t)(m0 + lr) * 1024 + lc;
    const bf16* pAl = Al + (size_t)(m0 + lr) * 1024 + lc;
    const bf16* pBh = Bh + (size_t)(n0 + lr) * 1024 + lc;
    const bf16* pBl = Bl + (size_t)(n0 + lr) * 1024 + lc;

    for (int kt = 0; kt < 32; ++kt) {
        __syncthreads();
        const int ko = kt * 32;
        *(uint4*)&sAh[lr][lc]     = *(const uint4*)(pAh + ko);
        *(uint4*)&sAh[lr][lc + 8] = *(const uint4*)(pAh + ko + 8);
        *(uint4*)&sAl[lr][lc]     = *(const uint4*)(pAl + ko);
        *(uint4*)&sAl[lr][lc + 8] = *(const uint4*)(pAl + ko + 8);
        *(uint4*)&sBh[lr][lc]     = *(const uint4*)(pBh + ko);
        *(uint4*)&sBh[lr][lc + 8] = *(const uint4*)(pBh + ko + 8);
        *(uint4*)&sBl[lr][lc]     = *(const uint4*)(pBl + ko);
        *(uint4*)&sBl[lr][lc + 8] = *(const uint4*)(pBl + ko + 8);
        __syncthreads();

#pragma unroll
        for (int kk = 0; kk < 32; kk += 16) {
            uint32_t ah[2][4], al[2][4];
#pragma unroll
            for (int mt = 0; mt < 2; ++mt) {
                const int r = wm + mt * 16;
                ah[mt][0] = *(const uint32_t*)&sAh[r + g][kk + 2 * qq];
                ah[mt][1] = *(const uint32_t*)&sAh[r + g + 8][kk + 2 * qq];
                ah[mt][2] = *(const uint32_t*)&sAh[r + g][kk + 2 * qq + 8];
                ah[mt][3] = *(const uint32_t*)&sAh[r + g + 8][kk + 2 * qq + 8];
                al[mt][0] = *(const uint32_t*)&sAl[r + g][kk + 2 * qq];
                al[mt][1] = *(const uint32_t*)&sAl[r + g + 8][kk + 2 * qq];
                al[mt][2] = *(const uint32_t*)&sAl[r + g][kk + 2 * qq + 8];
                al[mt][3] = *(const uint32_t*)&sAl[r + g + 8][kk + 2 * qq + 8];
            }
#pragma unroll
            for (int nt = 0; nt < 8; ++nt) {
                const int c = wn + nt * 8;
                uint32_t bh[2], bl[2];
                bh[0] = *(const uint32_t*)&sBh[c + g][kk + 2 * qq];
                bh[1] = *(const uint32_t*)&sBh[c + g][kk + 2 * qq + 8];
                bl[0] = *(const uint32_t*)&sBl[c + g][kk + 2 * qq];
                bl[1] = *(const uint32_t*)&sBl[c + g][kk + 2 * qq + 8];
#pragma unroll
                for (int mt = 0; mt < 2; ++mt) {
                    mma_bf16(acc[mt][nt], ah[mt], bh);
                    mma_bf16(acc[mt][nt], ah[mt], bl);
                    mma_bf16(acc[mt][nt], al[mt], bh);
                }
            }
        }
    }

#pragma unroll
    for (int mt = 0; mt < 2; ++mt) {
        const int r0 = m0 + wm + mt * 16 + g;
#pragma unroll
        for (int nt = 0; nt < 8; ++nt) {
            const int c = n0 + wn + nt * 8 + 2 * qq;
            float bx = 0.f, by = 0.f;
            if (bias) { bx = bias[c]; by = bias[c + 1]; }
            float2 v0 = make_float2(acc[mt][nt][0] + bx, acc[mt][nt][1] + by);
            float2 v1 = make_float2(acc[mt][nt][2] + bx, acc[mt][nt][3] + by);
            *(float2*)&C[(size_t)r0 * 1024 + c] = v0;
            *(float2*)&C[(size_t)(r0 + 8) * 1024 + c] = v1;
        }
    }
}

__global__ __launch_bounds__(256) void gemm_qkv(
    const float* dummy)   // pointers come from globals
{
    if (blockIdx.z == 0)
        gemm_mma_body(g_qh, g_ql, g_wqh, g_wql, g_Qf, nullptr);
    else if (blockIdx.z == 1)
        gemm_mma_body(g_kh, g_kl, g_wkh, g_wkl, g_Kf, nullptr);
    else
        gemm_mma_body(g_vh, g_vl, g_wvh, g_wvl, g_Vf, nullptr);
}

__global__ __launch_bounds__(256) void gemm_out(float* __restrict__ out,
                                                const float* __restrict__ bias)
{
    gemm_mma_body(g_ctxh, g_ctxl, g_woh, g_wol, out, bias);
}

// ------------------- RoPE: fp32 Q/K -> rotated bf16 hi/lo ------------------
__global__ __launch_bounds__(256) void rope_kernel()
{
    const int idx = blockIdx.x * 256 + threadIdx.x;   // < 2048*512
    const int s = idx >> 9;
    const int r = idx & 511;
    const int h = r >> 5;
    const int d = r & 31;

    const float inv_freq = expf(-(float)d * 0.28782313662425572f);
    float si, co;
    sincosf((float)s * inv_freq, &si, &co);

    const int base = s * DMODEL + h * DK + d;

    float x1 = g_Qf[base], x2 = g_Qf[base + 32];
    float o1 = x1 * co - x2 * si;
    float o2 = x2 * co + x1 * si;
    bf16 hh, ll;
    split2(o1, hh, ll); g_Qh[base] = hh;      g_Ql[base] = ll;
    split2(o2, hh, ll); g_Qh[base + 32] = hh; g_Ql[base + 32] = ll;

    x1 = g_Kf[base]; x2 = g_Kf[base + 32];
    o1 = x1 * co - x2 * si;
    o2 = x2 * co + x1 * si;
    split2(o1, hh, ll); g_Kh[base] = hh;      g_Kl[base] = ll;
    split2(o2, hh, ll); g_Kh[base + 32] = hh; g_Kl[base + 32] = ll;
}

// ---------------- V transpose: fp32 [s][1024] -> bf16 Vt [1024][2048] ------
__global__ __launch_bounds__(256) void vtrans_kernel()
{
    __shared__ float t[32][33];
    const int s0 = blockIdx.x * 32;
    const int d0 = blockIdx.y * 32;
    const int tid = threadIdx.x;
    const int r = tid >> 3;
    const int c4 = (tid & 7) * 4;

    float4 v = *(const float4*)&g_Vf[(size_t)(s0 + r) * 1024 + d0 + c4];
    t[r][c4 + 0] = v.x; t[r][c4 + 1] = v.y;
    t[r][c4 + 2] = v.z; t[r][c4 + 3] = v.w;
    __syncthreads();

    // write rows d = d0 + r, cols s = s0 + c4 .. +3
    float x0 = t[c4 + 0][r], x1 = t[c4 + 1][r];
    float x2 = t[c4 + 2][r], x3 = t[c4 + 3][r];
    bf16 h0, h1, h2, h3, l0, l1, l2, l3;
    split2(x0, h0, l0); split2(x1, h1, l1);
    split2(x2, h2, l2); split2(x3, h3, l3);
    uint32_t* ph = (uint32_t*)&g_Vth[(size_t)(d0 + r) * 2048 + s0 + c4];
    uint32_t* pl = (uint32_t*)&g_Vtl[(size_t)(d0 + r) * 2048 + s0 + c4];
    ph[0] = pack_bf16(__bfloat162float(h0), __bfloat162float(h1));
    ph[1] = pack_bf16(__bfloat162float(h2), __bfloat162float(h3));
    pl[0] = pack_bf16(__bfloat162float(l0), __bfloat162float(l1));
    pl[1] = pack_bf16(__bfloat162float(l2), __bfloat162float(l3));
}

// ---------------------------- attention (mma) ------------------------------
// block = (128 q rows, 1 head); 8 warps, warp = 16 q rows; k-tiles of 64.
__global__ __launch_bounds__(256) void attn_mma(float* __restrict__ attn,
                                                bf16* __restrict__ ctxh,
                                                bf16* __restrict__ ctxl)
{
    __shared__ bf16 sKh[64][72], sKl[64][72], sVh[64][72], sVl[64][72];

    const int h = blockIdx.y;
    const int q0 = blockIdx.x * 128;
    const int tid = threadIdx.x;
    const int w = tid >> 5, lane = tid & 31;
    const int g = lane >> 2, qq = lane & 3;
    const int qrow = q0 + w * 16;

    // persistent Q fragments (hi/lo), 4 k16 chunks over d=64
    uint32_t qfh[4][4], qfl[4][4];
#pragma unroll
    for (int kd = 0; kd < 4; ++kd) {
        const size_t b0 = (size_t)(qrow + g) * 1024 + h * 64 + kd * 16 + 2 * qq;
        const size_t b1 = b0 + (size_t)8 * 1024;
        qfh[kd][0] = *(const uint32_t*)&g_Qh[b0];
        qfh[kd][1] = *(const uint32_t*)&g_Qh[b1];
        qfh[kd][2] = *(const uint32_t*)&g_Qh[b0 + 8];
        qfh[kd][3] = *(const uint32_t*)&g_Qh[b1 + 8];
        qfl[kd][0] = *(const uint32_t*)&g_Ql[b0];
        qfl[kd][1] = *(const uint32_t*)&g_Ql[b1];
        qfl[kd][2] = *(const uint32_t*)&g_Ql[b0 + 8];
        qfl[kd][3] = *(const uint32_t*)&g_Ql[b1 + 8];
    }

    float ctx[8][4];
#pragma unroll
    for (int dt = 0; dt < 8; ++dt)
#pragma unroll
        for (int e = 0; e < 4; ++e) ctx[dt][e] = 0.f;
    float rs0 = 0.f, rs1 = 0.f;

    const int ldr = tid >> 2;           // 0..63
    const int ldo = (tid & 3) * 16;     // 0,16,32,48

    for (int kt = 0; kt < 32; ++kt) {
        const int k0 = kt * 64;
        __syncthreads();
        {
            const size_t kb = (size_t)(k0 + ldr) * 1024 + h * 64 + ldo;
            *(uint4*)&sKh[ldr][ldo]     = *(const uint4*)&g_Kh[kb];
            *(uint4*)&sKh[ldr][ldo + 8] = *(const uint4*)&g_Kh[kb + 8];
            *(uint4*)&sKl[ldr][ldo]     = *(const uint4*)&g_Kl[kb];
            *(uint4*)&sKl[ldr][ldo + 8] = *(const uint4*)&g_Kl[kb + 8];
            const size_t vb = (size_t)(h * 64 + ldr) * 2048 + k0 + ldo;
            *(uint4*)&sVh[ldr][ldo]     = *(const uint4*)&g_Vth[vb];
            *(uint4*)&sVh[ldr][ldo + 8] = *(const uint4*)&g_Vth[vb + 8];
            *(uint4*)&sVl[ldr][ldo]     = *(const uint4*)&g_Vtl[vb];
            *(uint4*)&sVl[ldr][ldo + 8] = *(const uint4*)&g_Vtl[vb + 8];
        }
        __syncthreads();

        // S = Q @ K^T  (16 x 64 per warp)
        float s[8][4];
#pragma unroll
        for (int nt = 0; nt < 8; ++nt)
#pragma unroll
            for (int e = 0; e < 4; ++e) s[nt][e] = 0.f;

#pragma unroll
        for (int kd = 0; kd < 4; ++kd) {
#pragma unroll
            for (int nt = 0; nt < 8; ++nt) {
                uint32_t bh[2], bl[2];
                bh[0] = *(const uint32_t*)&sKh[nt * 8 + g][kd * 16 + 2 * qq];
                bh[1] = *(const uint32_t*)&sKh[nt * 8 + g][kd * 16 + 2 * qq + 8];
                bl[0] = *(const uint32_t*)&sKl[nt * 8 + g][kd * 16 + 2 * qq];
                bl[1] = *(const uint32_t*)&sKl[nt * 8 + g][kd * 16 + 2 * qq + 8];
                mma_bf16(s[nt], qfh[kd], bh);
                mma_bf16(s[nt], qfh[kd], bl);
                mma_bf16(s[nt], qfl[kd], bh);
            }
        }

        // softmax numerator + attn store + pack P (hi/lo)
        uint32_t ph[8][2], pl[8][2];
#pragma unroll
        for (int nt = 0; nt < 8; ++nt) {
            float e0 = __expf(s[nt][0] * 0.125f);
            float e1 = __expf(s[nt][1] * 0.125f);
            float e2 = __expf(s[nt][2] * 0.125f);
            float e3 = __expf(s[nt][3] * 0.125f);
            rs0 += e0 + e1;
            rs1 += e2 + e3;
            const size_t arow = (size_t)(h * 2048 + qrow + g) * 2048
                                + k0 + nt * 8 + 2 * qq;
            *(float2*)&attn[arow] = make_float2(e0, e1);
            *(float2*)&attn[arow + (size_t)8 * 2048] = make_float2(e2, e3);

            float h0 = __bfloat162float(__float2bfloat16_rn(e0));
            float h1 = __bfloat162float(__float2bfloat16_rn(e1));
            float h2 = __bfloat162float(__float2bfloat16_rn(e2));
            float h3 = __bfloat162float(__float2bfloat16_rn(e3));
            ph[nt][0] = pack_bf16(h0, h1);
            ph[nt][1] = pack_bf16(h2, h3);
            pl[nt][0] = pack_bf16(e0 - h0, e1 - h1);
            pl[nt][1] = pack_bf16(e2 - h2, e3 - h3);
        }

        // ctx += P @ V   (A = P from register repack, B = Vt)
#pragma unroll
        for (int c = 0; c < 4; ++c) {
            uint32_t pah[4] = {ph[2 * c][0], ph[2 * c][1],
                               ph[2 * c + 1][0], ph[2 * c + 1][1]};
            uint32_t pal[4] = {pl[2 * c][0], pl[2 * c][1],
                               pl[2 * c + 1][0], pl[2 * c + 1][1]};
#pragma unroll
            for (int dt = 0; dt < 8; ++dt) {
                uint32_t vh[2], vl[2];
                vh[0] = *(const uint32_t*)&sVh[dt * 8 + g][c * 16 + 2 * qq];
                vh[1] = *(const uint32_t*)&sVh[dt * 8 + g][c * 16 + 2 * qq + 8];
                vl[0] = *(const uint32_t*)&sVl[dt * 8 + g][c * 16 + 2 * qq];
                vl[1] = *(const uint32_t*)&sVl[dt * 8 + g][c * 16 + 2 * qq + 8];
                mma_bf16(ctx[dt], pah, vh);
                mma_bf16(ctx[dt], pah, vl);
                mma_bf16(ctx[dt], pal, vh);
            }
        }
    }

    // row-sum reduce across the 4 lanes sharing a row
    rs0 += __shfl_xor_sync(0xffffffffu, rs0, 1);
    rs0 += __shfl_xor_sync(0xffffffffu, rs0, 2);
    rs1 += __shfl_xor_sync(0xffffffffu, rs1, 1);
    rs1 += __shfl_xor_sync(0xffffffffu, rs1, 2);
    const float inv0 = 1.f / rs0;
    const float inv1 = 1.f / rs1;

    // ctx epilogue -> bf16 hi/lo
#pragma unroll
    for (int dt = 0; dt < 8; ++dt) {
        const int col = h * 64 + dt * 8 + 2 * qq;
        float c0 = ctx[dt][0] * inv0, c1 = ctx[dt][1] * inv0;
        float c2 = ctx[dt][2] * inv1, c3 = ctx[dt][3] * inv1;
        float h0 = __bfloat162float(__float2bfloat16_rn(c0));
        float h1 = __bfloat162float(__float2bfloat16_rn(c1));
        float h2 = __bfloat162float(__float2bfloat16_rn(c2));
        float h3 = __bfloat162float(__float2bfloat16_rn(c3));
        const size_t r0 = (size_t)(qrow + g) * 1024 + col;
        const size_t r1 = (size_t)(qrow + g + 8) * 1024 + col;
        *(uint32_t*)&ctxh[r0] = pack_bf16(h0, h1);
        *(uint32_t*)&ctxh[r1] = pack_bf16(h2, h3);
        *(uint32_t*)&ctxl[r0] = pack_bf16(c0 - h0, c1 - h1);
        *(uint32_t*)&ctxl[r1] = pack_bf16(c2 - h2, c3 - h3);
    }

    // normalize the attn rows this warp owns (coalesced float4 sweep)
    __syncwarp();
#pragma unroll 1
    for (int r = 0; r < 16; ++r) {
        const float iv = (r < 8)
            ? __shfl_sync(0xffffffffu, inv0, r * 4)
            : __shfl_sync(0xffffffffu, inv1, (r - 8) * 4);
        float4* p = (float4*)&attn[(size_t)(h * 2048 + qrow + r) * 2048];
        for (int i = lane; i < 512; i += 32) {
            float4 v = p[i];
            v.x *= iv; v.y *= iv; v.z *= iv; v.w *= iv;
            p[i] = v;
        }
    }
}

// ---------------------------------------------------------------------------

extern "C" void kernel_launch(void* const* d_in, const int* in_sizes, int n_in,
                              void* d_out, int out_size)
{
    const float* q_in = (const float*)d_in[0];
    const float* k_in = (const float*)d_in[1];
    const float* v_in = (const float*)d_in[2];
    const float* w_q  = (const float*)d_in[3];
    const float* w_k  = (const float*)d_in[4];
    const float* w_v  = (const float*)d_in[5];
    const float* w_o  = (const float*)d_in[6];
    const float* b_o  = (const float*)d_in[7];
    float* out = (float*)d_out;

    const long long OUT_E  = (long long)S_LEN * DMODEL;
    const long long ATTN_E = (long long)NHEADS * S_LEN * S_LEN;
    float* attn = out + OUT_E;   // out_size always includes attn (verified R0/R1)
    (void)ATTN_E;

    bf16 *pCtxh, *pCtxl;
    cudaGetSymbolAddress((void**)&pCtxh, g_ctxh);
    cudaGetSymbolAddress((void**)&pCtxl, g_ctxl);

    // 1. convert inputs + weights to bf16 hi/lo
    conv_kernel<<<dim3(2048, 1, 7), 256>>>(q_in, k_in, v_in, w_q, w_k, w_v, w_o);
    // 2. QKV projections (bf16x3 mma) -> fp32 Q,K,V
    gemm_qkv<<<dim3(16, 8, 3), 256>>>(nullptr);
    // 3. RoPE -> bf16 hi/lo Q,K ; V transpose -> bf16 hi/lo Vt
    rope_kernel<<<4096, 256>>>();
    vtrans_kernel<<<dim3(64, 32), 256>>>();
    // 4. attention
    attn_mma<<<dim3(16, 16), 256>>>(attn, pCtxh, pCtxl);
    // 5. output projection
    gemm_out<<<dim3(16, 8), 256>>>(out, b_o);
}